// round 4
// baseline (speedup 1.0000x reference)
#include <cuda_runtime.h>
#include <math.h>

typedef unsigned long long ull;

#define H_DIM 64
#define W_DIM 64
#define B_DIM 64
#define R_DIM 128
#define D2    256
#define LPOS  (63*63)

// scratch (device globals; no runtime allocation)
__device__ float g_S[(size_t)H_DIM * W_DIM * B_DIM * R_DIM];  // [cell][b][r]
__device__ float g_A[(size_t)B_DIM * D2 * D2];
__device__ float g_y[(size_t)B_DIM * D2];

// ---------------------------------------------------------------------------
// packed fp32x2 helpers
// ---------------------------------------------------------------------------
__device__ __forceinline__ ull ffma2(ull a, ull b, ull c)
{
    ull d;
    asm("fma.rn.f32x2 %0, %1, %2, %3;" : "=l"(d) : "l"(a), "l"(b), "l"(c));
    return d;
}
__device__ __forceinline__ ull fadd2(ull a, ull b)
{
    ull d;
    asm("add.rn.f32x2 %0, %1, %2;" : "=l"(d) : "l"(a), "l"(b));
    return d;
}
__device__ __forceinline__ float2 unpack2(ull v)
{
    float2 r;
    asm("mov.b64 {%0, %1}, %2;" : "=f"(r.x), "=f"(r.y) : "l"(v));
    return r;
}
__device__ __forceinline__ ull pack2(float a, float b)
{
    ull d;
    asm("mov.b64 %0, {%1, %2};" : "=l"(d) : "f"(a), "f"(b));
    return d;
}

// ---------------------------------------------------------------------------
// Kernel 1: ESN recurrence, one CTA per batch.  512 threads.
// Thread t: r = t>>2 (output unit), q = t&3 (k-quarter).
//   q 0,1 -> W1 (left state), packed-k base (q&1)*32
//   q 2,3 -> W2 (above state)
// Weights live in registers (32 packed pairs / thread).  State rows live in
// shared memory, double buffered; per-cell: 32 ffma2 + shuffle reduce + tanh
// + one __syncthreads.  Row dumped to g_S coalesced after completion.
// ---------------------------------------------------------------------------
__global__ __launch_bounds__(512, 1) void esn_batch(
    const float* __restrict__ x, const float* __restrict__ Win,
    const float* __restrict__ W1, const float* __restrict__ W2)
{
    extern __shared__ float rbuf[];          // [2][64][128] floats = 64KB
    const int b = blockIdx.x;
    const int t = threadIdx.x;
    const int r = t >> 2;
    const int q = t & 3;

    // one-time weight load into registers, packed (W[2k][r], W[2k+1][r])
    const float* Wsrc = (q < 2) ? W1 : W2;
    const int qb = (q & 1) * 32;             // packed-k base within the matrix
    ull wreg[32];
#pragma unroll
    for (int i = 0; i < 32; i++) {
        const int k = 2 * (qb + i);
        wreg[i] = pack2(Wsrc[k * R_DIM + r], Wsrc[(k + 1) * R_DIM + r]);
    }
    const float winr = Win[r];
    const float* xb = x + ((size_t)b << 12);

    for (int h = 0; h < H_DIM; h++) {
        float* above = rbuf + (((h & 1) ^ 1) << 13);
        float* cur   = rbuf + ((h & 1) << 13);
        const bool okA = (h > 0);

        for (int w = 0; w < W_DIM; w++) {
            const bool act = (q < 2) ? (w > 0) : okA;
            const int wsafe = (w > 0) ? (w - 1) : 0;
            const float2* src = (q < 2)
                ? (const float2*)(cur + (wsafe << 7)) + qb
                : (const float2*)(above + (w << 7)) + qb;

            ull acc0 = 0ull, acc1 = 0ull, acc2 = 0ull, acc3 = 0ull;
            if (act) {
#pragma unroll
                for (int i = 0; i < 32; i += 4) {
                    const ulonglong2 s01 = *(const ulonglong2*)(src + i);
                    const ulonglong2 s23 = *(const ulonglong2*)(src + i + 2);
                    acc0 = ffma2(s01.x, wreg[i],     acc0);
                    acc1 = ffma2(s01.y, wreg[i + 1], acc1);
                    acc2 = ffma2(s23.x, wreg[i + 2], acc2);
                    acc3 = ffma2(s23.y, wreg[i + 3], acc3);
                }
            }
            const float2 sv = unpack2(fadd2(fadd2(acc0, acc1), fadd2(acc2, acc3)));
            float partial = sv.x + sv.y;
            partial += __shfl_xor_sync(0xffffffffu, partial, 1);
            partial += __shfl_xor_sync(0xffffffffu, partial, 2);

            if (q == 0) {
                const float xv = __ldg(xb + (h << 6) + w);
                cur[(w << 7) + r] = tanhf(fmaf(xv, winr, partial));
            }
            __syncthreads();
        }

        // dump row h to g_S[cell][b][r], coalesced.  No trailing barrier
        // needed: next row only READS this buffer (as `above`) and writes the
        // opposite one; first overwrite of this buffer is h+2, after the
        // per-cell barriers of row h+1 have drained every thread's stores.
        const float4* s4 = (const float4*)cur;
        float4* g4 = (float4*)g_S;
        for (int u = t; u < 2048; u += 512) {
            const int w_ = u >> 5, qd = u & 31;
            g4[(size_t)(((h << 6) + w_) * 64 + b) * 32 + qd] = s4[u];
        }
    }
}

// ---------------------------------------------------------------------------
// Kernel 2: XtX, symmetric, f32x2.  grid = (10 tile-pairs, 64 batches).
// ---------------------------------------------------------------------------
__global__ __launch_bounds__(256) void xtx_kernel()
{
    const int b = blockIdx.y;
    const int p = blockIdx.x;
    const int ti = (p < 4) ? 0 : (p < 7) ? 1 : (p < 9) ? 2 : 3;
    const int tbase = (ti == 0) ? 0 : (ti == 1) ? 4 : (ti == 2) ? 7 : 9;
    const int tj = ti + (p - tbase);

    const int t = threadIdx.x;
    const int di0 = (t & 15) << 2;
    const int dj0 = (t >> 4) << 2;

    __shared__ float  sA [16][64];
    __shared__ float2 sBd[16][64];

    ull acc[2][4];
#pragma unroll
    for (int pp = 0; pp < 2; pp++)
#pragma unroll
        for (int j = 0; j < 4; j++) acc[pp][j] = 0ull;

    const int lr = t >> 4;
    const int qq = t & 15;

#pragma unroll 1
    for (int l0 = 0; l0 < LPOS; l0 += 16) {
        __syncthreads();
        const int l = l0 + lr;
        float4 va = make_float4(0.f, 0.f, 0.f, 0.f);
        float4 vb = make_float4(0.f, 0.f, 0.f, 0.f);
        if (l < LPOS) {
            const int i = l / 63;
            const int j = l - i * 63;
            {
                const int cell = (ti < 2) ? ((i + 1) * W_DIM + j) : (i * W_DIM + j + 1);
                const int off  = (ti & 1) << 6;
                va = *(const float4*)(g_S + (((size_t)cell << 6) + b) * R_DIM + off + (qq << 2));
            }
            {
                const int cell = (tj < 2) ? ((i + 1) * W_DIM + j) : (i * W_DIM + j + 1);
                const int off  = (tj & 1) << 6;
                vb = *(const float4*)(g_S + (((size_t)cell << 6) + b) * R_DIM + off + (qq << 2));
            }
        }
        *(float4*)&sA[lr][qq << 2] = va;
        sBd[lr][(qq << 2) + 0] = make_float2(vb.x, vb.x);
        sBd[lr][(qq << 2) + 1] = make_float2(vb.y, vb.y);
        sBd[lr][(qq << 2) + 2] = make_float2(vb.z, vb.z);
        sBd[lr][(qq << 2) + 3] = make_float2(vb.w, vb.w);
        __syncthreads();

#pragma unroll
        for (int l2 = 0; l2 < 16; l2++) {
            const ulonglong2 av  = *(const ulonglong2*)&sA[l2][di0];
            const ulonglong2 b01 = *(const ulonglong2*)&sBd[l2][dj0];
            const ulonglong2 b23 = *(const ulonglong2*)&sBd[l2][dj0 + 2];
            acc[0][0] = ffma2(av.x, b01.x, acc[0][0]);
            acc[1][0] = ffma2(av.y, b01.x, acc[1][0]);
            acc[0][1] = ffma2(av.x, b01.y, acc[0][1]);
            acc[1][1] = ffma2(av.y, b01.y, acc[1][1]);
            acc[0][2] = ffma2(av.x, b23.x, acc[0][2]);
            acc[1][2] = ffma2(av.y, b23.x, acc[1][2]);
            acc[0][3] = ffma2(av.x, b23.y, acc[0][3]);
            acc[1][3] = ffma2(av.y, b23.y, acc[1][3]);
        }
    }

    float c[4][4];
#pragma unroll
    for (int pp = 0; pp < 2; pp++)
#pragma unroll
        for (int j = 0; j < 4; j++) {
            const float2 v = unpack2(acc[pp][j]);
            c[2 * pp][j] = v.x;
            c[2 * pp + 1][j] = v.y;
        }

    const size_t base = (size_t)b * D2 * D2;
#pragma unroll
    for (int ii = 0; ii < 4; ii++)
        *(float4*)(g_A + base + (size_t)(ti * 64 + di0 + ii) * D2 + tj * 64 + dj0) =
            make_float4(c[ii][0], c[ii][1], c[ii][2], c[ii][3]);
    if (ti != tj) {
#pragma unroll
        for (int jj = 0; jj < 4; jj++)
            *(float4*)(g_A + base + (size_t)(tj * 64 + dj0 + jj) * D2 + ti * 64 + di0) =
                make_float4(c[0][jj], c[1][jj], c[2][jj], c[3][jj]);
    }
}

// ---------------------------------------------------------------------------
// Kernel 3: Xty
// ---------------------------------------------------------------------------
__global__ __launch_bounds__(256) void xty_kernel(const float* __restrict__ x)
{
    const int b    = blockIdx.x;
    const int dd   = threadIdx.x;
    const int half = dd >> 7;
    const int r    = dd & 127;

    float acc = 0.0f;
#pragma unroll 1
    for (int i = 0; i < 63; i++) {
        const float* tgt_row = x + (size_t)b * (H_DIM * W_DIM) + (i + 1) * W_DIM + 1;
#pragma unroll 4
        for (int j = 0; j < 63; j++) {
            const int cell = (half == 0) ? ((i + 1) * W_DIM + j) : (i * W_DIM + j + 1);
            const float v = g_S[((size_t)cell * B_DIM + b) * R_DIM + r];
            acc = fmaf(v, tgt_row[j], acc);
        }
    }
    g_y[(size_t)b * D2 + dd] = acc;
}

// ---------------------------------------------------------------------------
// Kernel 4: blocked Cholesky solve (NB=32), packed lower triangle in smem.
// ---------------------------------------------------------------------------
#define PK_ELEMS (D2 * (D2 + 1) / 2)                 // 32896
#define LP_STRIDE 36
#define LP_FLOATS (224 * LP_STRIDE)                  // 8064
#define SOLVE_SMEM ((PK_ELEMS + LP_FLOATS + 4 * D2) * 4)

__device__ __forceinline__ int pkrow(int i) { return (i * (i + 1)) >> 1; }

__device__ __forceinline__ int tri_row(int e)
{
    int a = (int)((sqrtf(8.0f * (float)e + 1.0f) - 1.0f) * 0.5f);
    while (pkrow(a) > e) a--;
    while (pkrow(a + 1) <= e) a++;
    return a;
}

__global__ __launch_bounds__(256) void solve_kernel(float* __restrict__ out)
{
    extern __shared__ float sm[];
    float* P   = sm;
    float* Lp  = sm + PK_ELEMS;
    float* dgv = Lp + LP_FLOATS;
    float* riv = dgv + D2;
    float* zz  = riv + D2;
    float* xs  = zz + D2;

    const int b = blockIdx.x;
    const int t = threadIdx.x;
    const float* A = g_A + (size_t)b * D2 * D2;

    // load packed lower triangle + ridge
#pragma unroll 1
    for (int i = 0; i < D2; i++) {
        const int base = pkrow(i);
        for (int j = t; j <= i; j += 256)
            P[base + j] = A[(size_t)i * D2 + j] + ((j == i) ? 0.9f : 0.0f);
    }
    zz[t] = g_y[(size_t)b * D2 + t];
    __syncthreads();

#pragma unroll 1
    for (int kb = 0; kb < 8; kb++) {
        const int base = kb * 32;

        // ---- factor 32x32 diagonal block ----
#pragma unroll 1
        for (int j = 0; j < 32; j++) {
            const int jj = base + j;
            const float dj = sqrtf(P[pkrow(jj) + jj]);   // stable since last sync
            const float ri = 1.0f / dj;
            if (t == 0) { dgv[jj] = dj; riv[jj] = ri; }
            if (t > j && t < 32) P[pkrow(base + t) + jj] *= ri;
            __syncthreads();
            const int rem = 31 - j;
            const int cnt = (rem * (rem + 1)) >> 1;
            for (int e = t; e < cnt; e += 256) {
                const int a = tri_row(e);
                const int mloc = e - pkrow(a);
                const int i = base + j + 1 + a;
                const int m = base + j + 1 + mloc;
                P[pkrow(i) + m] -= P[pkrow(i) + jj] * P[pkrow(m) + jj];
            }
            __syncthreads();
        }

        const int rows = D2 - base - 32;
        if (rows > 0) {
            // ---- panel triangular solve: one row per thread, no syncs ----
            if (t < rows) {
                const int gi = base + 32 + t;
                const int rb = pkrow(gi) + base;
                float v[32];
#pragma unroll
                for (int m = 0; m < 32; m++) v[m] = P[rb + m];
#pragma unroll
                for (int j = 0; j < 32; j++) {
                    float s = v[j];
                    const int lb = pkrow(base + j) + base;
#pragma unroll
                    for (int m = 0; m < 32; m++) {
                        if (m < j) s -= v[m] * P[lb + m];
                    }
                    v[j] = s * riv[base + j];
                }
#pragma unroll
                for (int m = 0; m < 32; m++) {
                    P[rb + m] = v[m];
                    Lp[t * LP_STRIDE + m] = v[m];
                }
            }
            __syncthreads();

            // ---- trailing update: A22 -= L21 L21^T ----
            const int cnt = (rows * (rows + 1)) >> 1;
            for (int e = t; e < cnt; e += 256) {
                const int a = tri_row(e);
                const int jloc = e - pkrow(a);
                const float4* ra = (const float4*)(Lp + a * LP_STRIDE);
                const float4* rj = (const float4*)(Lp + jloc * LP_STRIDE);
                float s = 0.0f;
#pragma unroll
                for (int mm = 0; mm < 8; mm++) {
                    const float4 u4 = ra[mm];
                    const float4 v4 = rj[mm];
                    s = fmaf(u4.x, v4.x, s);
                    s = fmaf(u4.y, v4.y, s);
                    s = fmaf(u4.z, v4.z, s);
                    s = fmaf(u4.w, v4.w, s);
                }
                const int gi = base + 32 + a;
                const int gj = base + 32 + jloc;
                P[pkrow(gi) + gj] -= s;
            }
            __syncthreads();
        }
    }

    // forward solve L z = y
#pragma unroll 1
    for (int k = 0; k < D2; k++) {
        __syncthreads();
        const float xk = zz[k] * riv[k];
        if (t == k) xs[k] = xk;
        if (t > k)  zz[t] -= P[pkrow(t) + k] * xk;
    }
    __syncthreads();

    // backward solve L^T w = z
#pragma unroll 1
    for (int k = D2 - 1; k >= 0; k--) {
        __syncthreads();
        const float wk = xs[k] * riv[k];
        if (t == k) out[(size_t)b * D2 + k] = wk;
        if (t < k)  xs[t] -= P[pkrow(k) + t] * wk;
    }
}

// ---------------------------------------------------------------------------
// kernel_launch
// ---------------------------------------------------------------------------
#define ESN_SMEM 65536

extern "C" void kernel_launch(void* const* d_in, const int* in_sizes, int n_in,
                              void* d_out, int out_size)
{
    const float* x   = (const float*)d_in[0];
    const float* Win = (const float*)d_in[1];
    const float* W1  = (const float*)d_in[2];
    const float* W2  = (const float*)d_in[3];
    float* out = (float*)d_out;
    (void)in_sizes; (void)n_in; (void)out_size;

    cudaFuncSetAttribute(esn_batch,
                         cudaFuncAttributeMaxDynamicSharedMemorySize, ESN_SMEM);
    cudaFuncSetAttribute(solve_kernel,
                         cudaFuncAttributeMaxDynamicSharedMemorySize, SOLVE_SMEM);

    esn_batch<<<B_DIM, 512, ESN_SMEM>>>(x, Win, W1, W2);
    xtx_kernel<<<dim3(10, B_DIM), 256>>>();
    xty_kernel<<<B_DIM, 256>>>(x);
    solve_kernel<<<B_DIM, 256, SOLVE_SMEM>>>(out);
}

// round 5
// speedup vs baseline: 2.7140x; 2.7140x over previous
#include <cuda_runtime.h>
#include <math.h>

typedef unsigned long long ull;

#define H_DIM 64
#define W_DIM 64
#define B_DIM 64
#define R_DIM 128
#define D2    256
#define LPOS  (63*63)

// scratch (device globals; no runtime allocation)
__device__ float g_S[(size_t)H_DIM * W_DIM * B_DIM * R_DIM];  // [cell][b][r]
__device__ float g_A[(size_t)B_DIM * D2 * D2];
__device__ float g_y[(size_t)B_DIM * D2];

// ---------------------------------------------------------------------------
// packed fp32x2 helpers
// ---------------------------------------------------------------------------
__device__ __forceinline__ ull ffma2(ull a, ull b, ull c)
{
    ull d;
    asm("fma.rn.f32x2 %0, %1, %2, %3;" : "=l"(d) : "l"(a), "l"(b), "l"(c));
    return d;
}
__device__ __forceinline__ ull fadd2(ull a, ull b)
{
    ull d;
    asm("add.rn.f32x2 %0, %1, %2;" : "=l"(d) : "l"(a), "l"(b));
    return d;
}
__device__ __forceinline__ float2 unpack2(ull v)
{
    float2 r;
    asm("mov.b64 {%0, %1}, %2;" : "=f"(r.x), "=f"(r.y) : "l"(v));
    return r;
}
__device__ __forceinline__ ull pack2(float a, float b)
{
    ull d;
    asm("mov.b64 %0, {%1, %2};" : "=l"(d) : "f"(a), "f"(b));
    return d;
}

// ---------------------------------------------------------------------------
// Kernel 1: ESN recurrence, one CTA per batch.  1024 threads.
//   q  = t >> 6  : 16 k-groups of 16 k (q<8 -> W1/left, q>=8 -> W2/above)
//   rp = t & 63  : r-pair (r = 2rp, 2rp+1)
// Weights: 16 f32x2 pairs per thread in REGISTERS (32 regs -- no spill at the
// 64-reg cap).  States kept DUPLICATED (s,s) in smem so every warp lane reads
// the same address (pure broadcast, no bank conflicts).  Per cell:
// 16 FFMA2 -> red[q][rp] -> BAR -> 64 writers reduce 16-way, tanh, update
// dupL/rowdup and write g_S -> BAR.
// ---------------------------------------------------------------------------
#define ESN_SMEM ((64 * 128 * 8) + (128 * 8) + (16 * 64 * 8) + 256 + 256)

__global__ __launch_bounds__(1024, 1) void esn_batch(
    const float* __restrict__ x, const float* __restrict__ Win,
    const float* __restrict__ W1, const float* __restrict__ W2)
{
    extern __shared__ float sm[];
    float2* rowdup = (float2*)sm;                    // [64][128] dup above-row
    float2* dupL   = rowdup + 64 * 128;              // [128] dup left state
    ull*    red    = (ull*)(dupL + 128);             // [16][64] partial sums
    float*  xrow   = (float*)(red + 16 * 64);        // [64]

    const int b  = blockIdx.x;
    const int t  = threadIdx.x;
    const int q  = t >> 6;
    const int rp = t & 63;

    // one-time: weight pairs into registers. wreg[j] = (Wc[k][2rp], Wc[k][2rp+1])
    ull wreg[16];
    {
        const int kbase = q << 4;
#pragma unroll
        for (int j = 0; j < 16; j++) {
            const int k = kbase + j;
            const float* row = (k < 128) ? (W1 + k * R_DIM)
                                         : (W2 + (k - 128) * R_DIM);
            const float2 wp = *(const float2*)(row + (rp << 1));
            wreg[j] = pack2(wp.x, wp.y);
        }
    }
    float win0 = 0.f, win1 = 0.f;
    if (t < 64) {
        const float2 wp = *(const float2*)(Win + (t << 1));
        win0 = wp.x; win1 = wp.y;
    }
    const float* xb = x + ((size_t)b << 12);

    for (int h = 0; h < H_DIM; h++) {
        if (t < 64) xrow[t] = xb[(h << 6) + t];      // consumed after BAR1 of each cell

        for (int w = 0; w < W_DIM; w++) {
            const bool act = (q < 8) ? (w > 0) : (h > 0);
            const ulonglong2* src = (q < 8)
                ? (const ulonglong2*)(dupL + ((q) << 4))
                : (const ulonglong2*)(rowdup + (w << 7) + ((q - 8) << 4));

            ull a0 = 0ull, a1 = 0ull;
            if (act) {
#pragma unroll
                for (int i = 0; i < 8; i++) {
                    const ulonglong2 s = src[i];
                    a0 = ffma2(s.x, wreg[2 * i],     a0);
                    a1 = ffma2(s.y, wreg[2 * i + 1], a1);
                }
            }
            red[(q << 6) + rp] = fadd2(a0, a1);
            __syncthreads();

            if (t < 64) {
                ull s = red[t];
#pragma unroll 4
                for (int qq = 1; qq < 16; qq++)
                    s = fadd2(s, red[(qq << 6) + t]);
                const float2 v = unpack2(s);
                const float xv = xrow[w];
                const float s0 = tanhf(fmaf(xv, win0, v.x));
                const float s1 = tanhf(fmaf(xv, win1, v.y));
                const float2 d0 = make_float2(s0, s0);
                const float2 d1 = make_float2(s1, s1);
                dupL[2 * t]     = d0;
                dupL[2 * t + 1] = d1;
                rowdup[(w << 7) + 2 * t]     = d0;
                rowdup[(w << 7) + 2 * t + 1] = d1;
                *(float2*)(g_S + ((size_t)(((h << 6) + w) << 6) + b) * R_DIM + 2 * t)
                    = make_float2(s0, s1);
            }
            __syncthreads();
        }
    }
}

// ---------------------------------------------------------------------------
// Kernel 2: XtX, symmetric, f32x2.  grid = (10 tile-pairs, 64 batches).
// ---------------------------------------------------------------------------
__global__ __launch_bounds__(256) void xtx_kernel()
{
    const int b = blockIdx.y;
    const int p = blockIdx.x;
    const int ti = (p < 4) ? 0 : (p < 7) ? 1 : (p < 9) ? 2 : 3;
    const int tbase = (ti == 0) ? 0 : (ti == 1) ? 4 : (ti == 2) ? 7 : 9;
    const int tj = ti + (p - tbase);

    const int t = threadIdx.x;
    const int di0 = (t & 15) << 2;
    const int dj0 = (t >> 4) << 2;

    __shared__ float  sA [16][64];
    __shared__ float2 sBd[16][64];

    ull acc[2][4];
#pragma unroll
    for (int pp = 0; pp < 2; pp++)
#pragma unroll
        for (int j = 0; j < 4; j++) acc[pp][j] = 0ull;

    const int lr = t >> 4;
    const int qq = t & 15;

#pragma unroll 1
    for (int l0 = 0; l0 < LPOS; l0 += 16) {
        __syncthreads();
        const int l = l0 + lr;
        float4 va = make_float4(0.f, 0.f, 0.f, 0.f);
        float4 vb = make_float4(0.f, 0.f, 0.f, 0.f);
        if (l < LPOS) {
            const int i = l / 63;
            const int j = l - i * 63;
            {
                const int cell = (ti < 2) ? ((i + 1) * W_DIM + j) : (i * W_DIM + j + 1);
                const int off  = (ti & 1) << 6;
                va = *(const float4*)(g_S + (((size_t)cell << 6) + b) * R_DIM + off + (qq << 2));
            }
            {
                const int cell = (tj < 2) ? ((i + 1) * W_DIM + j) : (i * W_DIM + j + 1);
                const int off  = (tj & 1) << 6;
                vb = *(const float4*)(g_S + (((size_t)cell << 6) + b) * R_DIM + off + (qq << 2));
            }
        }
        *(float4*)&sA[lr][qq << 2] = va;
        sBd[lr][(qq << 2) + 0] = make_float2(vb.x, vb.x);
        sBd[lr][(qq << 2) + 1] = make_float2(vb.y, vb.y);
        sBd[lr][(qq << 2) + 2] = make_float2(vb.z, vb.z);
        sBd[lr][(qq << 2) + 3] = make_float2(vb.w, vb.w);
        __syncthreads();

#pragma unroll
        for (int l2 = 0; l2 < 16; l2++) {
            const ulonglong2 av  = *(const ulonglong2*)&sA[l2][di0];
            const ulonglong2 b01 = *(const ulonglong2*)&sBd[l2][dj0];
            const ulonglong2 b23 = *(const ulonglong2*)&sBd[l2][dj0 + 2];
            acc[0][0] = ffma2(av.x, b01.x, acc[0][0]);
            acc[1][0] = ffma2(av.y, b01.x, acc[1][0]);
            acc[0][1] = ffma2(av.x, b01.y, acc[0][1]);
            acc[1][1] = ffma2(av.y, b01.y, acc[1][1]);
            acc[0][2] = ffma2(av.x, b23.x, acc[0][2]);
            acc[1][2] = ffma2(av.y, b23.x, acc[1][2]);
            acc[0][3] = ffma2(av.x, b23.y, acc[0][3]);
            acc[1][3] = ffma2(av.y, b23.y, acc[1][3]);
        }
    }

    float c[4][4];
#pragma unroll
    for (int pp = 0; pp < 2; pp++)
#pragma unroll
        for (int j = 0; j < 4; j++) {
            const float2 v = unpack2(acc[pp][j]);
            c[2 * pp][j] = v.x;
            c[2 * pp + 1][j] = v.y;
        }

    const size_t base = (size_t)b * D2 * D2;
#pragma unroll
    for (int ii = 0; ii < 4; ii++)
        *(float4*)(g_A + base + (size_t)(ti * 64 + di0 + ii) * D2 + tj * 64 + dj0) =
            make_float4(c[ii][0], c[ii][1], c[ii][2], c[ii][3]);
    if (ti != tj) {
#pragma unroll
        for (int jj = 0; jj < 4; jj++)
            *(float4*)(g_A + base + (size_t)(tj * 64 + dj0 + jj) * D2 + ti * 64 + di0) =
                make_float4(c[0][jj], c[1][jj], c[2][jj], c[3][jj]);
    }
}

// ---------------------------------------------------------------------------
// Kernel 3: Xty
// ---------------------------------------------------------------------------
__global__ __launch_bounds__(256) void xty_kernel(const float* __restrict__ x)
{
    const int b    = blockIdx.x;
    const int dd   = threadIdx.x;
    const int half = dd >> 7;
    const int r    = dd & 127;

    float acc = 0.0f;
#pragma unroll 1
    for (int i = 0; i < 63; i++) {
        const float* tgt_row = x + (size_t)b * (H_DIM * W_DIM) + (i + 1) * W_DIM + 1;
#pragma unroll 4
        for (int j = 0; j < 63; j++) {
            const int cell = (half == 0) ? ((i + 1) * W_DIM + j) : (i * W_DIM + j + 1);
            const float v = g_S[((size_t)cell * B_DIM + b) * R_DIM + r];
            acc = fmaf(v, tgt_row[j], acc);
        }
    }
    g_y[(size_t)b * D2 + dd] = acc;
}

// ---------------------------------------------------------------------------
// Kernel 4: blocked Cholesky solve (NB=32), packed lower triangle in smem.
// ---------------------------------------------------------------------------
#define PK_ELEMS (D2 * (D2 + 1) / 2)                 // 32896
#define LP_STRIDE 36
#define LP_FLOATS (224 * LP_STRIDE)                  // 8064
#define SOLVE_SMEM ((PK_ELEMS + LP_FLOATS + 4 * D2) * 4)

__device__ __forceinline__ int pkrow(int i) { return (i * (i + 1)) >> 1; }

__device__ __forceinline__ int tri_row(int e)
{
    int a = (int)((sqrtf(8.0f * (float)e + 1.0f) - 1.0f) * 0.5f);
    while (pkrow(a) > e) a--;
    while (pkrow(a + 1) <= e) a++;
    return a;
}

__global__ __launch_bounds__(256) void solve_kernel(float* __restrict__ out)
{
    extern __shared__ float smref[];
    float* P   = smref;
    float* Lp  = smref + PK_ELEMS;
    float* dgv = Lp + LP_FLOATS;
    float* riv = dgv + D2;
    float* zz  = riv + D2;
    float* xs  = zz + D2;

    const int b = blockIdx.x;
    const int t = threadIdx.x;
    const float* A = g_A + (size_t)b * D2 * D2;

    // load packed lower triangle + ridge
#pragma unroll 1
    for (int i = 0; i < D2; i++) {
        const int base = pkrow(i);
        for (int j = t; j <= i; j += 256)
            P[base + j] = A[(size_t)i * D2 + j] + ((j == i) ? 0.9f : 0.0f);
    }
    zz[t] = g_y[(size_t)b * D2 + t];
    __syncthreads();

#pragma unroll 1
    for (int kb = 0; kb < 8; kb++) {
        const int base = kb * 32;

        // ---- factor 32x32 diagonal block ----
#pragma unroll 1
        for (int j = 0; j < 32; j++) {
            const int jj = base + j;
            const float dj = sqrtf(P[pkrow(jj) + jj]);   // stable since last sync
            const float ri = 1.0f / dj;
            if (t == 0) { dgv[jj] = dj; riv[jj] = ri; }
            if (t > j && t < 32) P[pkrow(base + t) + jj] *= ri;
            __syncthreads();
            const int rem = 31 - j;
            const int cnt = (rem * (rem + 1)) >> 1;
            for (int e = t; e < cnt; e += 256) {
                const int a = tri_row(e);
                const int mloc = e - pkrow(a);
                const int i = base + j + 1 + a;
                const int m = base + j + 1 + mloc;
                P[pkrow(i) + m] -= P[pkrow(i) + jj] * P[pkrow(m) + jj];
            }
            __syncthreads();
        }

        const int rows = D2 - base - 32;
        if (rows > 0) {
            // ---- panel triangular solve: one row per thread, no syncs ----
            if (t < rows) {
                const int gi = base + 32 + t;
                const int rb = pkrow(gi) + base;
                float v[32];
#pragma unroll
                for (int m = 0; m < 32; m++) v[m] = P[rb + m];
#pragma unroll
                for (int j = 0; j < 32; j++) {
                    float s = v[j];
                    const int lb = pkrow(base + j) + base;
#pragma unroll
                    for (int m = 0; m < 32; m++) {
                        if (m < j) s -= v[m] * P[lb + m];
                    }
                    v[j] = s * riv[base + j];
                }
#pragma unroll
                for (int m = 0; m < 32; m++) {
                    P[rb + m] = v[m];
                    Lp[t * LP_STRIDE + m] = v[m];
                }
            }
            __syncthreads();

            // ---- trailing update: A22 -= L21 L21^T ----
            const int cnt = (rows * (rows + 1)) >> 1;
            for (int e = t; e < cnt; e += 256) {
                const int a = tri_row(e);
                const int jloc = e - pkrow(a);
                const float4* ra = (const float4*)(Lp + a * LP_STRIDE);
                const float4* rj = (const float4*)(Lp + jloc * LP_STRIDE);
                float s = 0.0f;
#pragma unroll
                for (int mm = 0; mm < 8; mm++) {
                    const float4 u4 = ra[mm];
                    const float4 v4 = rj[mm];
                    s = fmaf(u4.x, v4.x, s);
                    s = fmaf(u4.y, v4.y, s);
                    s = fmaf(u4.z, v4.z, s);
                    s = fmaf(u4.w, v4.w, s);
                }
                const int gi = base + 32 + a;
                const int gj = base + 32 + jloc;
                P[pkrow(gi) + gj] -= s;
            }
            __syncthreads();
        }
    }

    // forward solve L z = y
#pragma unroll 1
    for (int k = 0; k < D2; k++) {
        __syncthreads();
        const float xk = zz[k] * riv[k];
        if (t == k) xs[k] = xk;
        if (t > k)  zz[t] -= P[pkrow(t) + k] * xk;
    }
    __syncthreads();

    // backward solve L^T w = z
#pragma unroll 1
    for (int k = D2 - 1; k >= 0; k--) {
        __syncthreads();
        const float wk = xs[k] * riv[k];
        if (t == k) out[(size_t)b * D2 + k] = wk;
        if (t < k)  xs[t] -= P[pkrow(k) + t] * wk;
    }
}

// ---------------------------------------------------------------------------
// kernel_launch
// ---------------------------------------------------------------------------
extern "C" void kernel_launch(void* const* d_in, const int* in_sizes, int n_in,
                              void* d_out, int out_size)
{
    const float* x   = (const float*)d_in[0];
    const float* Win = (const float*)d_in[1];
    const float* W1  = (const float*)d_in[2];
    const float* W2  = (const float*)d_in[3];
    float* out = (float*)d_out;
    (void)in_sizes; (void)n_in; (void)out_size;

    cudaFuncSetAttribute(esn_batch,
                         cudaFuncAttributeMaxDynamicSharedMemorySize, ESN_SMEM);
    cudaFuncSetAttribute(solve_kernel,
                         cudaFuncAttributeMaxDynamicSharedMemorySize, SOLVE_SMEM);

    esn_batch<<<B_DIM, 1024, ESN_SMEM>>>(x, Win, W1, W2);
    xtx_kernel<<<dim3(10, B_DIM), 256>>>();
    xty_kernel<<<B_DIM, 256>>>(x);
    solve_kernel<<<B_DIM, 256, SOLVE_SMEM>>>(out);
}

// round 6
// speedup vs baseline: 3.2630x; 1.2023x over previous
#include <cuda_runtime.h>
#include <math.h>

typedef unsigned long long ull;

#define H_DIM 64
#define W_DIM 64
#define B_DIM 64
#define R_DIM 128
#define D2    256
#define LPOS  (63*63)

// scratch (device globals; no runtime allocation)
__device__ float g_S[(size_t)H_DIM * W_DIM * B_DIM * R_DIM];  // [cell][b][r]
__device__ float g_A[(size_t)B_DIM * D2 * D2];
__device__ float g_y[(size_t)B_DIM * D2];

// ---------------------------------------------------------------------------
// packed fp32x2 helpers
// ---------------------------------------------------------------------------
__device__ __forceinline__ ull ffma2(ull a, ull b, ull c)
{
    ull d;
    asm("fma.rn.f32x2 %0, %1, %2, %3;" : "=l"(d) : "l"(a), "l"(b), "l"(c));
    return d;
}
__device__ __forceinline__ ull fadd2(ull a, ull b)
{
    ull d;
    asm("add.rn.f32x2 %0, %1, %2;" : "=l"(d) : "l"(a), "l"(b));
    return d;
}
__device__ __forceinline__ float2 unpack2(ull v)
{
    float2 r;
    asm("mov.b64 {%0, %1}, %2;" : "=f"(r.x), "=f"(r.y) : "l"(v));
    return r;
}
__device__ __forceinline__ ull pack2(float a, float b)
{
    ull d;
    asm("mov.b64 %0, {%1, %2};" : "=l"(d) : "f"(a), "f"(b));
    return d;
}

// ---------------------------------------------------------------------------
// Kernel 1: ESN recurrence, one CTA per batch, WAVEFRONT over anti-diagonals
// of the 64x64 grid (cells on a diagonal are independent: left & above both
// sit on diagonal d-1).  1024 threads:
//   q  = t >> 6  : 16 k-groups of 16 k (q<8 -> W1/left, q>=8 -> W2/above)
//   rp = t & 63  : r-pair; weights = 16 f32x2 register pairs per thread.
// Diagonal states live in two zero-initialized smem ring buffers of 65 slots
// (slot(h)=h+1); missing neighbors read hard zeros -- no predicates.
// Per chunk of <=8 cells: ph1 = 8x(8 bcast LDS + 16 FFMA2 + STS) per thread,
// BAR, ph2 = one (cell,r) output per thread (16-float reduce + tanh), BAR.
// ---------------------------------------------------------------------------
#define CCH 8
#define ESN_SMEM ((2 * 65 * 128 * 8) + (CCH * 16 * 64 * 8))   // 133120 + 65536

__global__ __launch_bounds__(1024, 1) void esn_wave(
    const float* __restrict__ x, const float* __restrict__ Win,
    const float* __restrict__ W1, const float* __restrict__ W2)
{
    extern __shared__ float sm[];
    float2* buf0 = (float2*)sm;               // [65][128] diag states (dup)
    float2* buf1 = buf0 + 65 * 128;
    ull*    red  = (ull*)(buf1 + 65 * 128);   // [CCH][16][64] partials

    const int b  = blockIdx.x;
    const int t  = threadIdx.x;
    const int q  = t >> 6;
    const int rp = t & 63;
    const int r  = t & 127;                   // ph2 identity (within half-chunk)

    // one-time: weight pairs into registers
    ull wreg[16];
    {
        const int kbase = q << 4;
#pragma unroll
        for (int j = 0; j < 16; j++) {
            const int k = kbase + j;
            const float* row = (k < 128) ? (W1 + k * R_DIM)
                                         : (W2 + (k - 128) * R_DIM);
            const float2 wp = *(const float2*)(row + (rp << 1));
            wreg[j] = pack2(wp.x, wp.y);
        }
    }
    const float winr = Win[r];
    const float* xb = x + ((size_t)b << 12);

    // zero both diagonal buffers (zero slots double as boundary guards)
    {
        float4* z = (float4*)sm;
        for (int u = t; u < (2 * 65 * 128 * 2) / 4; u += 1024)
            z[u] = make_float4(0.f, 0.f, 0.f, 0.f);
    }
    __syncthreads();

    for (int d = 0; d < H_DIM + W_DIM - 1; d++) {
        const int hmin = (d > 63) ? d - 63 : 0;
        const int hmax = (d < 63) ? d : 63;
        float2* prev = (d & 1) ? buf0 : buf1;
        float2* cur  = (d & 1) ? buf1 : buf0;

        for (int c0 = hmin; c0 <= hmax; c0 += CCH) {
            const int nc = (hmax - c0 + 1 < CCH) ? (hmax - c0 + 1) : CCH;

            // ---- phase 1: partial dot products, all 1024 threads ----
#pragma unroll 2
            for (int ci = 0; ci < CCH; ci++) {
                if (ci >= nc) break;
                const int h = c0 + ci;
                // left slot(h)=h+1 ; above slot(h-1)=h.  zero slots cover
                // w==0 (slot d+1 never written) and h==0 (slot 0).
                const ulonglong2* src = (q < 8)
                    ? (const ulonglong2*)(prev + (h + 1) * 128 + (q << 4))
                    : (const ulonglong2*)(prev + h * 128 + ((q - 8) << 4));
                ull a0 = 0ull, a1 = 0ull;
#pragma unroll
                for (int i = 0; i < 8; i++) {
                    const ulonglong2 s = src[i];
                    a0 = ffma2(s.x, wreg[2 * i],     a0);
                    a1 = ffma2(s.y, wreg[2 * i + 1], a1);
                }
                red[((ci << 4) + q) * 64 + rp] = fadd2(a0, a1);
            }
            __syncthreads();

            // ---- phase 2: one (cell, r) output per thread ----
            {
                const int ci = t >> 7;
                if (ci < nc) {
                    const int h = c0 + ci;
                    const int w = d - h;
                    const float* redf = (const float*)red + (ci << 11) + r;
                    float s0 = redf[0]        + redf[128];
                    float s1 = redf[2 * 128]  + redf[3 * 128];
                    float s2 = redf[4 * 128]  + redf[5 * 128];
                    float s3 = redf[6 * 128]  + redf[7 * 128];
                    float s4 = redf[8 * 128]  + redf[9 * 128];
                    float s5 = redf[10 * 128] + redf[11 * 128];
                    float s6 = redf[12 * 128] + redf[13 * 128];
                    float s7 = redf[14 * 128] + redf[15 * 128];
                    const float ssum = ((s0 + s1) + (s2 + s3))
                                     + ((s4 + s5) + (s6 + s7));
                    const float xv = __ldg(xb + (h << 6) + w);
                    const float sr = tanhf(fmaf(xv, winr, ssum));
                    cur[(h + 1) * 128 + r] = make_float2(sr, sr);
                    g_S[((size_t)(((h << 6) + w) << 6) + b) * R_DIM + r] = sr;
                }
            }
            __syncthreads();
        }
    }
}

// ---------------------------------------------------------------------------
// Kernel 2: XtX, symmetric, f32x2.  grid = (10 tile-pairs, 64 batches).
// ---------------------------------------------------------------------------
__global__ __launch_bounds__(256) void xtx_kernel()
{
    const int b = blockIdx.y;
    const int p = blockIdx.x;
    const int ti = (p < 4) ? 0 : (p < 7) ? 1 : (p < 9) ? 2 : 3;
    const int tbase = (ti == 0) ? 0 : (ti == 1) ? 4 : (ti == 2) ? 7 : 9;
    const int tj = ti + (p - tbase);

    const int t = threadIdx.x;
    const int di0 = (t & 15) << 2;
    const int dj0 = (t >> 4) << 2;

    __shared__ float  sA [16][64];
    __shared__ float2 sBd[16][64];

    ull acc[2][4];
#pragma unroll
    for (int pp = 0; pp < 2; pp++)
#pragma unroll
        for (int j = 0; j < 4; j++) acc[pp][j] = 0ull;

    const int lr = t >> 4;
    const int qq = t & 15;

#pragma unroll 1
    for (int l0 = 0; l0 < LPOS; l0 += 16) {
        __syncthreads();
        const int l = l0 + lr;
        float4 va = make_float4(0.f, 0.f, 0.f, 0.f);
        float4 vb = make_float4(0.f, 0.f, 0.f, 0.f);
        if (l < LPOS) {
            const int i = l / 63;
            const int j = l - i * 63;
            {
                const int cell = (ti < 2) ? ((i + 1) * W_DIM + j) : (i * W_DIM + j + 1);
                const int off  = (ti & 1) << 6;
                va = *(const float4*)(g_S + (((size_t)cell << 6) + b) * R_DIM + off + (qq << 2));
            }
            {
                const int cell = (tj < 2) ? ((i + 1) * W_DIM + j) : (i * W_DIM + j + 1);
                const int off  = (tj & 1) << 6;
                vb = *(const float4*)(g_S + (((size_t)cell << 6) + b) * R_DIM + off + (qq << 2));
            }
        }
        *(float4*)&sA[lr][qq << 2] = va;
        sBd[lr][(qq << 2) + 0] = make_float2(vb.x, vb.x);
        sBd[lr][(qq << 2) + 1] = make_float2(vb.y, vb.y);
        sBd[lr][(qq << 2) + 2] = make_float2(vb.z, vb.z);
        sBd[lr][(qq << 2) + 3] = make_float2(vb.w, vb.w);
        __syncthreads();

#pragma unroll
        for (int l2 = 0; l2 < 16; l2++) {
            const ulonglong2 av  = *(const ulonglong2*)&sA[l2][di0];
            const ulonglong2 b01 = *(const ulonglong2*)&sBd[l2][dj0];
            const ulonglong2 b23 = *(const ulonglong2*)&sBd[l2][dj0 + 2];
            acc[0][0] = ffma2(av.x, b01.x, acc[0][0]);
            acc[1][0] = ffma2(av.y, b01.x, acc[1][0]);
            acc[0][1] = ffma2(av.x, b01.y, acc[0][1]);
            acc[1][1] = ffma2(av.y, b01.y, acc[1][1]);
            acc[0][2] = ffma2(av.x, b23.x, acc[0][2]);
            acc[1][2] = ffma2(av.y, b23.x, acc[1][2]);
            acc[0][3] = ffma2(av.x, b23.y, acc[0][3]);
            acc[1][3] = ffma2(av.y, b23.y, acc[1][3]);
        }
    }

    float c[4][4];
#pragma unroll
    for (int pp = 0; pp < 2; pp++)
#pragma unroll
        for (int j = 0; j < 4; j++) {
            const float2 v = unpack2(acc[pp][j]);
            c[2 * pp][j] = v.x;
            c[2 * pp + 1][j] = v.y;
        }

    const size_t base = (size_t)b * D2 * D2;
#pragma unroll
    for (int ii = 0; ii < 4; ii++)
        *(float4*)(g_A + base + (size_t)(ti * 64 + di0 + ii) * D2 + tj * 64 + dj0) =
            make_float4(c[ii][0], c[ii][1], c[ii][2], c[ii][3]);
    if (ti != tj) {
#pragma unroll
        for (int jj = 0; jj < 4; jj++)
            *(float4*)(g_A + base + (size_t)(tj * 64 + dj0 + jj) * D2 + ti * 64 + di0) =
                make_float4(c[0][jj], c[1][jj], c[2][jj], c[3][jj]);
    }
}

// ---------------------------------------------------------------------------
// Kernel 3: Xty
// ---------------------------------------------------------------------------
__global__ __launch_bounds__(256) void xty_kernel(const float* __restrict__ x)
{
    const int b    = blockIdx.x;
    const int dd   = threadIdx.x;
    const int half = dd >> 7;
    const int r    = dd & 127;

    float acc = 0.0f;
#pragma unroll 1
    for (int i = 0; i < 63; i++) {
        const float* tgt_row = x + (size_t)b * (H_DIM * W_DIM) + (i + 1) * W_DIM + 1;
#pragma unroll 4
        for (int j = 0; j < 63; j++) {
            const int cell = (half == 0) ? ((i + 1) * W_DIM + j) : (i * W_DIM + j + 1);
            const float v = g_S[((size_t)cell * B_DIM + b) * R_DIM + r];
            acc = fmaf(v, tgt_row[j], acc);
        }
    }
    g_y[(size_t)b * D2 + dd] = acc;
}

// ---------------------------------------------------------------------------
// Kernel 4: blocked Cholesky solve (NB=32), packed lower triangle in smem.
// ---------------------------------------------------------------------------
#define PK_ELEMS (D2 * (D2 + 1) / 2)                 // 32896
#define LP_STRIDE 36
#define LP_FLOATS (224 * LP_STRIDE)                  // 8064
#define SOLVE_SMEM ((PK_ELEMS + LP_FLOATS + 4 * D2) * 4)

__device__ __forceinline__ int pkrow(int i) { return (i * (i + 1)) >> 1; }

__device__ __forceinline__ int tri_row(int e)
{
    int a = (int)((sqrtf(8.0f * (float)e + 1.0f) - 1.0f) * 0.5f);
    while (pkrow(a) > e) a--;
    while (pkrow(a + 1) <= e) a++;
    return a;
}

__global__ __launch_bounds__(256) void solve_kernel(float* __restrict__ out)
{
    extern __shared__ float smref[];
    float* P   = smref;
    float* Lp  = smref + PK_ELEMS;
    float* dgv = Lp + LP_FLOATS;
    float* riv = dgv + D2;
    float* zz  = riv + D2;
    float* xs  = zz + D2;

    const int b = blockIdx.x;
    const int t = threadIdx.x;
    const float* A = g_A + (size_t)b * D2 * D2;

    // load packed lower triangle + ridge
#pragma unroll 1
    for (int i = 0; i < D2; i++) {
        const int base = pkrow(i);
        for (int j = t; j <= i; j += 256)
            P[base + j] = A[(size_t)i * D2 + j] + ((j == i) ? 0.9f : 0.0f);
    }
    zz[t] = g_y[(size_t)b * D2 + t];
    __syncthreads();

#pragma unroll 1
    for (int kb = 0; kb < 8; kb++) {
        const int base = kb * 32;

        // ---- factor 32x32 diagonal block ----
#pragma unroll 1
        for (int j = 0; j < 32; j++) {
            const int jj = base + j;
            const float dj = sqrtf(P[pkrow(jj) + jj]);   // stable since last sync
            const float ri = 1.0f / dj;
            if (t == 0) { dgv[jj] = dj; riv[jj] = ri; }
            if (t > j && t < 32) P[pkrow(base + t) + jj] *= ri;
            __syncthreads();
            const int rem = 31 - j;
            const int cnt = (rem * (rem + 1)) >> 1;
            for (int e = t; e < cnt; e += 256) {
                const int a = tri_row(e);
                const int mloc = e - pkrow(a);
                const int i = base + j + 1 + a;
                const int m = base + j + 1 + mloc;
                P[pkrow(i) + m] -= P[pkrow(i) + jj] * P[pkrow(m) + jj];
            }
            __syncthreads();
        }

        const int rows = D2 - base - 32;
        if (rows > 0) {
            // ---- panel triangular solve: one row per thread, no syncs ----
            if (t < rows) {
                const int gi = base + 32 + t;
                const int rb = pkrow(gi) + base;
                float v[32];
#pragma unroll
                for (int m = 0; m < 32; m++) v[m] = P[rb + m];
#pragma unroll
                for (int j = 0; j < 32; j++) {
                    float s = v[j];
                    const int lb = pkrow(base + j) + base;
#pragma unroll
                    for (int m = 0; m < 32; m++) {
                        if (m < j) s -= v[m] * P[lb + m];
                    }
                    v[j] = s * riv[base + j];
                }
#pragma unroll
                for (int m = 0; m < 32; m++) {
                    P[rb + m] = v[m];
                    Lp[t * LP_STRIDE + m] = v[m];
                }
            }
            __syncthreads();

            // ---- trailing update: A22 -= L21 L21^T ----
            const int cnt = (rows * (rows + 1)) >> 1;
            for (int e = t; e < cnt; e += 256) {
                const int a = tri_row(e);
                const int jloc = e - pkrow(a);
                const float4* ra = (const float4*)(Lp + a * LP_STRIDE);
                const float4* rj = (const float4*)(Lp + jloc * LP_STRIDE);
                float s = 0.0f;
#pragma unroll
                for (int mm = 0; mm < 8; mm++) {
                    const float4 u4 = ra[mm];
                    const float4 v4 = rj[mm];
                    s = fmaf(u4.x, v4.x, s);
                    s = fmaf(u4.y, v4.y, s);
                    s = fmaf(u4.z, v4.z, s);
                    s = fmaf(u4.w, v4.w, s);
                }
                const int gi = base + 32 + a;
                const int gj = base + 32 + jloc;
                P[pkrow(gi) + gj] -= s;
            }
            __syncthreads();
        }
    }

    // forward solve L z = y
#pragma unroll 1
    for (int k = 0; k < D2; k++) {
        __syncthreads();
        const float xk = zz[k] * riv[k];
        if (t == k) xs[k] = xk;
        if (t > k)  zz[t] -= P[pkrow(t) + k] * xk;
    }
    __syncthreads();

    // backward solve L^T w = z
#pragma unroll 1
    for (int k = D2 - 1; k >= 0; k--) {
        __syncthreads();
        const float wk = xs[k] * riv[k];
        if (t == k) out[(size_t)b * D2 + k] = wk;
        if (t < k)  xs[t] -= P[pkrow(k) + t] * wk;
    }
}

// ---------------------------------------------------------------------------
// kernel_launch
// ---------------------------------------------------------------------------
extern "C" void kernel_launch(void* const* d_in, const int* in_sizes, int n_in,
                              void* d_out, int out_size)
{
    const float* x   = (const float*)d_in[0];
    const float* Win = (const float*)d_in[1];
    const float* W1  = (const float*)d_in[2];
    const float* W2  = (const float*)d_in[3];
    float* out = (float*)d_out;
    (void)in_sizes; (void)n_in; (void)out_size;

    cudaFuncSetAttribute(esn_wave,
                         cudaFuncAttributeMaxDynamicSharedMemorySize, ESN_SMEM);
    cudaFuncSetAttribute(solve_kernel,
                         cudaFuncAttributeMaxDynamicSharedMemorySize, SOLVE_SMEM);

    esn_wave<<<B_DIM, 1024, ESN_SMEM>>>(x, Win, W1, W2);
    xtx_kernel<<<dim3(10, B_DIM), 256>>>();
    xty_kernel<<<B_DIM, 256>>>(x);
    solve_kernel<<<B_DIM, 256, SOLVE_SMEM>>>(out);
}

// round 7
// speedup vs baseline: 3.7754x; 1.1570x over previous
#include <cuda_runtime.h>
#include <math.h>
#include <stdint.h>

typedef unsigned long long ull;

#define H_DIM 64
#define W_DIM 64
#define B_DIM 64
#define R_DIM 128
#define D2    256
#define LPOS  (63*63)

// scratch (device globals; no runtime allocation)
__device__ float g_S[(size_t)H_DIM * W_DIM * B_DIM * R_DIM];  // [cell][b][r]
__device__ float g_A[(size_t)B_DIM * D2 * D2];
__device__ float g_y[(size_t)B_DIM * D2];

// ---------------------------------------------------------------------------
// packed fp32x2 + cluster helpers
// ---------------------------------------------------------------------------
__device__ __forceinline__ ull ffma2(ull a, ull b, ull c)
{
    ull d;
    asm("fma.rn.f32x2 %0, %1, %2, %3;" : "=l"(d) : "l"(a), "l"(b), "l"(c));
    return d;
}
__device__ __forceinline__ ull fadd2(ull a, ull b)
{
    ull d;
    asm("add.rn.f32x2 %0, %1, %2;" : "=l"(d) : "l"(a), "l"(b));
    return d;
}
__device__ __forceinline__ float2 unpack2(ull v)
{
    float2 r;
    asm("mov.b64 {%0, %1}, %2;" : "=f"(r.x), "=f"(r.y) : "l"(v));
    return r;
}
__device__ __forceinline__ ull pack2(float a, float b)
{
    ull d;
    asm("mov.b64 %0, {%1, %2};" : "=l"(d) : "f"(a), "f"(b));
    return d;
}
__device__ __forceinline__ uint32_t smem_u32(const void* p)
{
    uint32_t a;
    asm("{ .reg .u64 t; cvta.to.shared.u64 t, %1; cvt.u32.u64 %0, t; }"
        : "=r"(a) : "l"(p));
    return a;
}
__device__ __forceinline__ void st_cluster_b64(uint32_t addr, ull v)
{
    asm volatile("st.shared::cluster.b64 [%0], %1;" :: "r"(addr), "l"(v) : "memory");
}
#define CLUSTER_SYNC() do { \
    asm volatile("barrier.cluster.arrive.aligned;" ::: "memory"); \
    asm volatile("barrier.cluster.wait.aligned;"   ::: "memory"); \
} while (0)

// ---------------------------------------------------------------------------
// Kernel 1: ESN recurrence.  2-CTA cluster per batch; each CTA computes the
// r-half [rank*64, rank*64+64) of every cell, wavefront over anti-diagonals.
// 1024 threads: q = t>>5 in [0,32): k-group of 8 (q<16 -> W1/left, else
// W2/above); rp = t&31: r-pair within my half.  Weights: 8 f32x2 register
// pairs per thread.  Diagonal states (FULL 128 r, duplicated (s,s)) in two
// zero-initialized 65-slot ring buffers; peer half arrives via DSMEM stores
// (st.shared::cluster) published by one cluster barrier per diagonal.
// ---------------------------------------------------------------------------
#define CCH 8
#define ESN_BUF_BYTES (65 * 128 * 8)
#define ESN_SMEM (2 * ESN_BUF_BYTES + CCH * 32 * 32 * 8)   // 133120 + 65536

__global__ __launch_bounds__(1024, 1) __cluster_dims__(2, 1, 1)
void esn_cluster(const float* __restrict__ x, const float* __restrict__ Win,
                 const float* __restrict__ W1, const float* __restrict__ W2)
{
    extern __shared__ float sm[];
    float2* buf0 = (float2*)sm;               // [65][128] diag states (dup)
    float2* buf1 = buf0 + 65 * 128;
    ull*    red  = (ull*)(buf1 + 65 * 128);   // [CCH][32][32] partials

    uint32_t rank;
    asm("mov.u32 %0, %%cluster_ctarank;" : "=r"(rank));
    const int b  = blockIdx.x >> 1;
    const int t  = threadIdx.x;
    const int q  = t >> 5;                    // 0..31
    const int rp = t & 31;                    // r-pair within my 64-r half

    const int rbase = (int)(rank << 6);
    const int kk = (q & 15) << 3;
    const float* Wsrc = (q < 16) ? W1 : W2;
    ull wreg[8];
#pragma unroll
    for (int j = 0; j < 8; j++) {
        const float2 wp = *(const float2*)(Wsrc + (kk + j) * R_DIM + rbase + (rp << 1));
        wreg[j] = pack2(wp.x, wp.y);
    }
    const float2 win2 = *(const float2*)(Win + rbase + (rp << 1));
    const float* xb = x + ((size_t)b << 12);

    const uint32_t my_base = smem_u32(sm);
    uint32_t peer_base;
    asm("mapa.shared::cluster.u32 %0, %1, %2;"
        : "=r"(peer_base) : "r"(my_base), "r"(rank ^ 1u));

    // zero both diagonal buffers (zero slots double as boundary guards)
    {
        float4* z = (float4*)sm;
        for (int u = t; u < (2 * ESN_BUF_BYTES) / 16; u += 1024)
            z[u] = make_float4(0.f, 0.f, 0.f, 0.f);
    }
    __syncthreads();
    CLUSTER_SYNC();   // peer zeroing done before our DSMEM stores can land

    for (int d = 0; d < H_DIM + W_DIM - 1; d++) {
        const int hmin = (d > 63) ? d - 63 : 0;
        const int hmax = (d < 63) ? d : 63;
        float2* prev = (d & 1) ? buf0 : buf1;
        float2* cur  = (d & 1) ? buf1 : buf0;
        const uint32_t cur_off = (d & 1) ? (uint32_t)ESN_BUF_BYTES : 0u;

        for (int c0 = hmin; c0 <= hmax; c0 += CCH) {
            const int nc = (hmax - c0 + 1 < CCH) ? (hmax - c0 + 1) : CCH;

            // ---- phase 1: partial dot products, all 1024 threads ----
#pragma unroll 2
            for (int ci = 0; ci < CCH; ci++) {
                if (ci >= nc) break;
                const int h = c0 + ci;
                // left slot(h)=h+1 ; above slot(h-1)=h ; unwritten slots are 0
                const int slot = (q < 16) ? (h + 1) : h;
                const ulonglong2* src = (const ulonglong2*)(prev + slot * 128 + kk);
                ull a0 = 0ull, a1 = 0ull;
#pragma unroll
                for (int i = 0; i < 4; i++) {
                    const ulonglong2 s = src[i];
                    a0 = ffma2(s.x, wreg[2 * i],     a0);
                    a1 = ffma2(s.y, wreg[2 * i + 1], a1);
                }
                red[((ci << 5) + q) * 32 + rp] = fadd2(a0, a1);
            }
            __syncthreads();

            // ---- phase 2: one (cell, r-pair) output per thread ----
            {
                const int ci = t >> 5;
                if (ci < nc) {
                    const int h = c0 + ci;
                    const int w = d - h;
                    const ull* rr = red + (ci << 10) + rp;
                    ull s0 = rr[0], s1 = rr[32], s2 = rr[64], s3 = rr[96];
#pragma unroll
                    for (int qq = 4; qq < 32; qq += 4) {
                        s0 = fadd2(s0, rr[(qq + 0) << 5]);
                        s1 = fadd2(s1, rr[(qq + 1) << 5]);
                        s2 = fadd2(s2, rr[(qq + 2) << 5]);
                        s3 = fadd2(s3, rr[(qq + 3) << 5]);
                    }
                    const float2 v = unpack2(fadd2(fadd2(s0, s1), fadd2(s2, s3)));
                    const float xv = __ldg(xb + (h << 6) + w);
                    const float o0 = tanhf(fmaf(xv, win2.x, v.x));
                    const float o1 = tanhf(fmaf(xv, win2.y, v.y));
                    const int r0  = rbase + (rp << 1);
                    const int idx = (h + 1) * 128 + r0;
                    cur[idx]     = make_float2(o0, o0);
                    cur[idx + 1] = make_float2(o1, o1);
                    const uint32_t poff = peer_base + cur_off + (uint32_t)idx * 8u;
                    st_cluster_b64(poff,      pack2(o0, o0));
                    st_cluster_b64(poff + 8u, pack2(o1, o1));
                    *(float2*)(g_S + ((size_t)(((h << 6) + w) << 6) + b) * R_DIM + r0)
                        = make_float2(o0, o1);
                }
            }
            __syncthreads();
        }
        CLUSTER_SYNC();   // publish DSMEM half-states before next diagonal reads
    }
}

// ---------------------------------------------------------------------------
// Kernel 2: XtX, symmetric, f32x2.  grid = (10 tile-pairs, 64 batches).
// ---------------------------------------------------------------------------
__global__ __launch_bounds__(256) void xtx_kernel()
{
    const int b = blockIdx.y;
    const int p = blockIdx.x;
    const int ti = (p < 4) ? 0 : (p < 7) ? 1 : (p < 9) ? 2 : 3;
    const int tbase = (ti == 0) ? 0 : (ti == 1) ? 4 : (ti == 2) ? 7 : 9;
    const int tj = ti + (p - tbase);

    const int t = threadIdx.x;
    const int di0 = (t & 15) << 2;
    const int dj0 = (t >> 4) << 2;

    __shared__ float  sA [16][64];
    __shared__ float2 sBd[16][64];

    ull acc[2][4];
#pragma unroll
    for (int pp = 0; pp < 2; pp++)
#pragma unroll
        for (int j = 0; j < 4; j++) acc[pp][j] = 0ull;

    const int lr = t >> 4;
    const int qq = t & 15;

#pragma unroll 1
    for (int l0 = 0; l0 < LPOS; l0 += 16) {
        __syncthreads();
        const int l = l0 + lr;
        float4 va = make_float4(0.f, 0.f, 0.f, 0.f);
        float4 vb = make_float4(0.f, 0.f, 0.f, 0.f);
        if (l < LPOS) {
            const int i = l / 63;
            const int j = l - i * 63;
            {
                const int cell = (ti < 2) ? ((i + 1) * W_DIM + j) : (i * W_DIM + j + 1);
                const int off  = (ti & 1) << 6;
                va = *(const float4*)(g_S + (((size_t)cell << 6) + b) * R_DIM + off + (qq << 2));
            }
            {
                const int cell = (tj < 2) ? ((i + 1) * W_DIM + j) : (i * W_DIM + j + 1);
                const int off  = (tj & 1) << 6;
                vb = *(const float4*)(g_S + (((size_t)cell << 6) + b) * R_DIM + off + (qq << 2));
            }
        }
        *(float4*)&sA[lr][qq << 2] = va;
        sBd[lr][(qq << 2) + 0] = make_float2(vb.x, vb.x);
        sBd[lr][(qq << 2) + 1] = make_float2(vb.y, vb.y);
        sBd[lr][(qq << 2) + 2] = make_float2(vb.z, vb.z);
        sBd[lr][(qq << 2) + 3] = make_float2(vb.w, vb.w);
        __syncthreads();

#pragma unroll
        for (int l2 = 0; l2 < 16; l2++) {
            const ulonglong2 av  = *(const ulonglong2*)&sA[l2][di0];
            const ulonglong2 b01 = *(const ulonglong2*)&sBd[l2][dj0];
            const ulonglong2 b23 = *(const ulonglong2*)&sBd[l2][dj0 + 2];
            acc[0][0] = ffma2(av.x, b01.x, acc[0][0]);
            acc[1][0] = ffma2(av.y, b01.x, acc[1][0]);
            acc[0][1] = ffma2(av.x, b01.y, acc[0][1]);
            acc[1][1] = ffma2(av.y, b01.y, acc[1][1]);
            acc[0][2] = ffma2(av.x, b23.x, acc[0][2]);
            acc[1][2] = ffma2(av.y, b23.x, acc[1][2]);
            acc[0][3] = ffma2(av.x, b23.y, acc[0][3]);
            acc[1][3] = ffma2(av.y, b23.y, acc[1][3]);
        }
    }

    float c[4][4];
#pragma unroll
    for (int pp = 0; pp < 2; pp++)
#pragma unroll
        for (int j = 0; j < 4; j++) {
            const float2 v = unpack2(acc[pp][j]);
            c[2 * pp][j] = v.x;
            c[2 * pp + 1][j] = v.y;
        }

    const size_t base = (size_t)b * D2 * D2;
#pragma unroll
    for (int ii = 0; ii < 4; ii++)
        *(float4*)(g_A + base + (size_t)(ti * 64 + di0 + ii) * D2 + tj * 64 + dj0) =
            make_float4(c[ii][0], c[ii][1], c[ii][2], c[ii][3]);
    if (ti != tj) {
#pragma unroll
        for (int jj = 0; jj < 4; jj++)
            *(float4*)(g_A + base + (size_t)(tj * 64 + dj0 + jj) * D2 + ti * 64 + di0) =
                make_float4(c[0][jj], c[1][jj], c[2][jj], c[3][jj]);
    }
}

// ---------------------------------------------------------------------------
// Kernel 3: Xty
// ---------------------------------------------------------------------------
__global__ __launch_bounds__(256) void xty_kernel(const float* __restrict__ x)
{
    const int b    = blockIdx.x;
    const int dd   = threadIdx.x;
    const int half = dd >> 7;
    const int r    = dd & 127;

    float acc = 0.0f;
#pragma unroll 1
    for (int i = 0; i < 63; i++) {
        const float* tgt_row = x + (size_t)b * (H_DIM * W_DIM) + (i + 1) * W_DIM + 1;
#pragma unroll 4
        for (int j = 0; j < 63; j++) {
            const int cell = (half == 0) ? ((i + 1) * W_DIM + j) : (i * W_DIM + j + 1);
            const float v = g_S[((size_t)cell * B_DIM + b) * R_DIM + r];
            acc = fmaf(v, tgt_row[j], acc);
        }
    }
    g_y[(size_t)b * D2 + dd] = acc;
}

// ---------------------------------------------------------------------------
// Kernel 4: blocked Cholesky solve (NB=32), packed lower triangle in smem.
// ---------------------------------------------------------------------------
#define PK_ELEMS (D2 * (D2 + 1) / 2)                 // 32896
#define LP_STRIDE 36
#define LP_FLOATS (224 * LP_STRIDE)                  // 8064
#define SOLVE_SMEM ((PK_ELEMS + LP_FLOATS + 4 * D2) * 4)

__device__ __forceinline__ int pkrow(int i) { return (i * (i + 1)) >> 1; }

__device__ __forceinline__ int tri_row(int e)
{
    int a = (int)((sqrtf(8.0f * (float)e + 1.0f) - 1.0f) * 0.5f);
    while (pkrow(a) > e) a--;
    while (pkrow(a + 1) <= e) a++;
    return a;
}

__global__ __launch_bounds__(256) void solve_kernel(float* __restrict__ out)
{
    extern __shared__ float smref[];
    float* P   = smref;
    float* Lp  = smref + PK_ELEMS;
    float* dgv = Lp + LP_FLOATS;
    float* riv = dgv + D2;
    float* zz  = riv + D2;
    float* xs  = zz + D2;

    const int b = blockIdx.x;
    const int t = threadIdx.x;
    const float* A = g_A + (size_t)b * D2 * D2;

    // load packed lower triangle + ridge
#pragma unroll 1
    for (int i = 0; i < D2; i++) {
        const int base = pkrow(i);
        for (int j = t; j <= i; j += 256)
            P[base + j] = A[(size_t)i * D2 + j] + ((j == i) ? 0.9f : 0.0f);
    }
    zz[t] = g_y[(size_t)b * D2 + t];
    __syncthreads();

#pragma unroll 1
    for (int kb = 0; kb < 8; kb++) {
        const int base = kb * 32;

        // ---- factor 32x32 diagonal block ----
#pragma unroll 1
        for (int j = 0; j < 32; j++) {
            const int jj = base + j;
            const float dj = sqrtf(P[pkrow(jj) + jj]);   // stable since last sync
            const float ri = 1.0f / dj;
            if (t == 0) { dgv[jj] = dj; riv[jj] = ri; }
            if (t > j && t < 32) P[pkrow(base + t) + jj] *= ri;
            __syncthreads();
            const int rem = 31 - j;
            const int cnt = (rem * (rem + 1)) >> 1;
            for (int e = t; e < cnt; e += 256) {
                const int a = tri_row(e);
                const int mloc = e - pkrow(a);
                const int i = base + j + 1 + a;
                const int m = base + j + 1 + mloc;
                P[pkrow(i) + m] -= P[pkrow(i) + jj] * P[pkrow(m) + jj];
            }
            __syncthreads();
        }

        const int rows = D2 - base - 32;
        if (rows > 0) {
            // ---- panel triangular solve: one row per thread, no syncs ----
            if (t < rows) {
                const int gi = base + 32 + t;
                const int rb = pkrow(gi) + base;
                float v[32];
#pragma unroll
                for (int m = 0; m < 32; m++) v[m] = P[rb + m];
#pragma unroll
                for (int j = 0; j < 32; j++) {
                    float s = v[j];
                    const int lb = pkrow(base + j) + base;
#pragma unroll
                    for (int m = 0; m < 32; m++) {
                        if (m < j) s -= v[m] * P[lb + m];
                    }
                    v[j] = s * riv[base + j];
                }
#pragma unroll
                for (int m = 0; m < 32; m++) {
                    P[rb + m] = v[m];
                    Lp[t * LP_STRIDE + m] = v[m];
                }
            }
            __syncthreads();

            // ---- trailing update: A22 -= L21 L21^T ----
            const int cnt = (rows * (rows + 1)) >> 1;
            for (int e = t; e < cnt; e += 256) {
                const int a = tri_row(e);
                const int jloc = e - pkrow(a);
                const float4* ra = (const float4*)(Lp + a * LP_STRIDE);
                const float4* rj = (const float4*)(Lp + jloc * LP_STRIDE);
                float s = 0.0f;
#pragma unroll
                for (int mm = 0; mm < 8; mm++) {
                    const float4 u4 = ra[mm];
                    const float4 v4 = rj[mm];
                    s = fmaf(u4.x, v4.x, s);
                    s = fmaf(u4.y, v4.y, s);
                    s = fmaf(u4.z, v4.z, s);
                    s = fmaf(u4.w, v4.w, s);
                }
                const int gi = base + 32 + a;
                const int gj = base + 32 + jloc;
                P[pkrow(gi) + gj] -= s;
            }
            __syncthreads();
        }
    }

    // forward solve L z = y
#pragma unroll 1
    for (int k = 0; k < D2; k++) {
        __syncthreads();
        const float xk = zz[k] * riv[k];
        if (t == k) xs[k] = xk;
        if (t > k)  zz[t] -= P[pkrow(t) + k] * xk;
    }
    __syncthreads();

    // backward solve L^T w = z
#pragma unroll 1
    for (int k = D2 - 1; k >= 0; k--) {
        __syncthreads();
        const float wk = xs[k] * riv[k];
        if (t == k) out[(size_t)b * D2 + k] = wk;
        if (t < k)  xs[t] -= P[pkrow(k) + t] * wk;
    }
}

// ---------------------------------------------------------------------------
// kernel_launch
// ---------------------------------------------------------------------------
extern "C" void kernel_launch(void* const* d_in, const int* in_sizes, int n_in,
                              void* d_out, int out_size)
{
    const float* x   = (const float*)d_in[0];
    const float* Win = (const float*)d_in[1];
    const float* W1  = (const float*)d_in[2];
    const float* W2  = (const float*)d_in[3];
    float* out = (float*)d_out;
    (void)in_sizes; (void)n_in; (void)out_size;

    cudaFuncSetAttribute(esn_cluster,
                         cudaFuncAttributeMaxDynamicSharedMemorySize, ESN_SMEM);
    cudaFuncSetAttribute(solve_kernel,
                         cudaFuncAttributeMaxDynamicSharedMemorySize, SOLVE_SMEM);

    esn_cluster<<<2 * B_DIM, 1024, ESN_SMEM>>>(x, Win, W1, W2);
    xtx_kernel<<<dim3(10, B_DIM), 256>>>();
    xty_kernel<<<B_DIM, 256>>>(x);
    solve_kernel<<<B_DIM, 256, SOLVE_SMEM>>>(out);
}